// round 5
// baseline (speedup 1.0000x reference)
#include <cuda_runtime.h>

#define IMG_W 512
#define IMG_H 512
#define PLANES 64
#define PLANE_STRIDE (IMG_H * IMG_W)
#define NPIX (PLANES * PLANE_STRIDE)
#define STRIP 16
#define STRIPS (IMG_H / STRIP)          // 32
#define NBLOCKS (PLANES * STRIPS)       // 2048
#define EPS 1e-10f

// persistent scratch (statically zero-initialized; reset by last block each call)
__device__ double g_acc;
__device__ unsigned int g_count;

__global__ void __launch_bounds__(128, 12) ngf_kernel(
    const float* __restrict__ I0, const float* __restrict__ I1,
    float* __restrict__ out)
{
    const int t     = threadIdx.x;            // 0..127, one float4 column-group
    const int lane  = t & 31;
    const int plane = blockIdx.x >> 5;        // / STRIPS
    const int strip = blockIdx.x & (STRIPS - 1);
    const int col   = t << 2;                 // 0..508

    const float* __restrict__ p0 = I0 + plane * PLANE_STRIDE + col;
    const float* __restrict__ p1 = I1 + plane * PLANE_STRIDE + col;

    const int rbase = strip * STRIP;
    const int rup   = (rbase > 0) ? rbase - 1 : 0;
    const int rdn   = rbase + 1;              // rbase+1 <= 497, always in range

    // rolling rows: up = row max(r-1,0), cen = row r, dn = row min(r+1,511)
    float4 up0  = *(const float4*)(p0 + rup * IMG_W);
    float4 up1  = *(const float4*)(p1 + rup * IMG_W);
    float4 cen0 = *(const float4*)(p0 + rbase * IMG_W);
    float4 cen1 = *(const float4*)(p1 + rbase * IMG_W);
    float4 dn0  = *(const float4*)(p0 + rdn * IMG_W);
    float4 dn1  = *(const float4*)(p1 + rdn * IMG_W);

    // running pointers to current row (for warp-edge halo scalars)
    const float* pr0 = p0 + rbase * IMG_W;
    const float* pr1 = p1 + rbase * IMG_W;

    const bool leftEdge  = (col == 0);
    const bool rightEdge = (col + 4 == IMG_W);

    float s0 = 0.f, s1 = 0.f;

#pragma unroll 4
    for (int r = rbase; r < rbase + STRIP; ++r) {
        // lookahead: next iteration's dn row (clamped at bottom)
        int rn = r + 2;
        if (rn > IMG_H - 1) rn = IMG_H - 1;
        const float4 ndn0 = *(const float4*)(p0 + rn * IMG_W);
        const float4 ndn1 = *(const float4*)(p1 + rn * IMG_W);

        // horizontal halo: neighbor lanes via shfl; warp-edge lanes patch
        // with an (L1/L2-hit) scalar load, clamped at image edge
        float hl0 = __shfl_up_sync(0xFFFFFFFFu, cen0.w, 1);
        float hr0 = __shfl_down_sync(0xFFFFFFFFu, cen0.x, 1);
        float hl1 = __shfl_up_sync(0xFFFFFFFFu, cen1.w, 1);
        float hr1 = __shfl_down_sync(0xFFFFFFFFu, cen1.x, 1);
        if (lane == 0) {
            hl0 = leftEdge ? cen0.x : pr0[-1];
            hl1 = leftEdge ? cen1.x : pr1[-1];
        }
        if (lane == 31) {
            hr0 = rightEdge ? cen0.w : pr0[4];
            hr1 = rightEdge ? cen1.w : pr1[4];
        }

        // gx = x[min(r+1)] - x[max(r-1)]   (fwd/central/bwd diff)
        const float g0x[4] = { dn0.x - up0.x, dn0.y - up0.y, dn0.z - up0.z, dn0.w - up0.w };
        const float g1x[4] = { dn1.x - up1.x, dn1.y - up1.y, dn1.z - up1.z, dn1.w - up1.w };
        // gy = x[min(c+1)] - x[max(c-1)]
        const float g0y[4] = { cen0.y - hl0, cen0.z - cen0.x, cen0.w - cen0.y, hr0 - cen0.z };
        const float g1y[4] = { cen1.y - hl1, cen1.z - cen1.x, cen1.w - cen1.y, hr1 - cen1.z };

#pragma unroll
        for (int i = 0; i < 4; i++) {
            const float n0  = fmaf(g0x[i], g0x[i], fmaf(g0y[i], g0y[i], EPS));
            const float n1  = fmaf(g1x[i], g1x[i], fmaf(g1y[i], g1y[i], EPS));
            const float dot = fmaf(g0x[i], g1x[i], g0y[i] * g1y[i]);
            // dot^2/(n0*n1) == (g0/|g0| . g1/|g1|)^2
            const float v = __fdividef(dot * dot, n0 * n1);
            if (i & 1) s1 += v; else s0 += v;
        }

        // rotate rows, advance halo pointers
        up0 = cen0; cen0 = dn0; dn0 = ndn0;
        up1 = cen1; cen1 = dn1; dn1 = ndn1;
        pr0 += IMG_W; pr1 += IMG_W;
    }

    float s = s0 + s1;

    // warp reduction
#pragma unroll
    for (int off = 16; off > 0; off >>= 1)
        s += __shfl_xor_sync(0xFFFFFFFFu, s, off);

    __shared__ float warp_part[4];
    const int wid = t >> 5;
    if (lane == 0) warp_part[wid] = s;
    __syncthreads();

    if (t == 0) {
        const double bs = (double)warp_part[0] + (double)warp_part[1]
                        + (double)warp_part[2] + (double)warp_part[3];
        atomicAdd(&g_acc, bs);
        __threadfence();
        const unsigned prev = atomicAdd(&g_count, 1u);
        if (prev == NBLOCKS - 1) {
            // last block: all adds visible (atomics serialize at L2)
            const double total = atomicAdd(&g_acc, 0.0);
            out[0] = (float)(1.0 - total / (double)NPIX);
            // reset for next graph replay (deterministic)
            g_acc = 0.0;
            g_count = 0u;
            __threadfence();
        }
    }
}

extern "C" void kernel_launch(void* const* d_in, const int* in_sizes, int n_in,
                              void* d_out, int out_size)
{
    const float* I0 = (const float*)d_in[0];
    const float* I1 = (const float*)d_in[1];
    float* out = (float*)d_out;

    ngf_kernel<<<NBLOCKS, 128>>>(I0, I1, out);
}

// round 6
// speedup vs baseline: 2.0611x; 2.0611x over previous
#include <cuda_runtime.h>
#include <cstdint>

#define IMG_W 512
#define IMG_H 512
#define PLANES 64
#define PLANE_STRIDE (IMG_H * IMG_W)
#define NPIX (PLANES * PLANE_STRIDE)
#define STRIP 16
#define STRIPS (IMG_H / STRIP)           // 32
#define NBLOCKS (PLANES * STRIPS)        // 2048
#define NSLOT 10                         // smem row-ring slots (per image pair)
#define EPS 1e-10f

// persistent scratch (statically zero-init; last block resets each call)
__device__ double g_acc;
__device__ unsigned int g_count;

__device__ __forceinline__ void cp16(uint32_t dst, const float* src) {
    asm volatile("cp.async.cg.shared.global [%0], [%1], 16;" :: "r"(dst), "l"(src) : "memory");
}
__device__ __forceinline__ void cp_commit() {
    asm volatile("cp.async.commit_group;" ::: "memory");
}
__device__ __forceinline__ void cp_wait2() {
    asm volatile("cp.async.wait_group 2;" ::: "memory");
}

__global__ void __launch_bounds__(256, 5) ngf_kernel(
    const float* __restrict__ I0, const float* __restrict__ I1,
    float* __restrict__ out)
{
    // ring: slot s holds one global row for both images: [img0: 512 f][img1: 512 f]
    __shared__ float ring[NSLOT * 1024];
    __shared__ float warp_part[8];

    const int t    = threadIdx.x;
    const int lane = t & 31;
    const int cg   = t & 127;            // float4 column group 0..127
    const int h    = t >> 7;             // 0/1: load-image role AND compute-row-half role
    const int plane = blockIdx.x >> 5;
    const int strip = blockIdx.x & (STRIPS - 1);
    const int R0    = strip * STRIP;

    // producer role: this thread copies rows of image h
    const float* __restrict__ lbase =
        (h ? I1 : I0) + plane * PLANE_STRIDE;

    const uint32_t sring = (uint32_t)__cvta_generic_to_shared(ring);

    // group j copies rows k = 2j, 2j+1 (global row g = clamp(R0-1+k)) for this thread's image
    #define ISSUE_GROUP(j)                                                        \
        do {                                                                      \
            _Pragma("unroll")                                                     \
            for (int q = 0; q < 2; q++) {                                         \
                const int k = 2 * (j) + q;                                        \
                int g = R0 - 1 + k;                                               \
                g = (g < 0) ? 0 : ((g > IMG_H - 1) ? IMG_H - 1 : g);              \
                const uint32_t dst = sring + (uint32_t)((k % NSLOT) * 4096        \
                                   + h * 2048 + cg * 16);                         \
                cp16(dst, lbase + g * IMG_W + cg * 4);                            \
            }                                                                     \
            cp_commit();                                                          \
        } while (0)

    // prologue: groups 0..2 (rows k=0..5)
    ISSUE_GROUP(0);
    ISSUE_GROUP(1);
    ISSUE_GROUP(2);

    float s = 0.f;

    for (int i = 0; i < 8; i++) {
        // keep group count uniform so wait_group 2 tracks real groups
        if (i < 6) ISSUE_GROUP(3 + i);
        else       cp_commit();

        cp_wait2();          // rows k <= 2i+3 complete (covers dn of row 2i+1)
        __syncthreads();     // make all threads' copies visible

        // ---- compute row r = R0 + 2i + h ----
        const int kc = 2 * i + h + 1;                       // k of center row
        const float* upr = ring + ((kc - 1) % NSLOT) * 1024;
        const float* cer = ring + ( kc      % NSLOT) * 1024;
        const float* dnr = ring + ((kc + 1) % NSLOT) * 1024;

        const float4 up0 = ((const float4*)upr)[cg];
        const float4 up1 = ((const float4*)(upr + 512))[cg];
        const float4 ce0 = ((const float4*)cer)[cg];
        const float4 ce1 = ((const float4*)(cer + 512))[cg];
        const float4 dn0 = ((const float4*)dnr)[cg];
        const float4 dn1 = ((const float4*)(dnr + 512))[cg];

        // horizontal halo: shfl interior, lane-edge patch from smem (clamped idx)
        float hl0 = __shfl_up_sync(0xFFFFFFFFu, ce0.w, 1);
        float hr0 = __shfl_down_sync(0xFFFFFFFFu, ce0.x, 1);
        float hl1 = __shfl_up_sync(0xFFFFFFFFu, ce1.w, 1);
        float hr1 = __shfl_down_sync(0xFFFFFFFFu, ce1.x, 1);
        if (lane == 0) {
            const int il = (4 * cg - 1 < 0) ? 0 : 4 * cg - 1;
            hl0 = cer[il];
            hl1 = cer[512 + il];
        }
        if (lane == 31) {
            const int ir = (4 * cg + 4 > IMG_W - 1) ? IMG_W - 1 : 4 * cg + 4;
            hr0 = cer[ir];
            hr1 = cer[512 + ir];
        }

        // gx = x[min(r+1)] - x[max(r-1)]   (rows were loaded clamped)
        const float g0x[4] = { dn0.x - up0.x, dn0.y - up0.y, dn0.z - up0.z, dn0.w - up0.w };
        const float g1x[4] = { dn1.x - up1.x, dn1.y - up1.y, dn1.z - up1.z, dn1.w - up1.w };
        // gy = x[min(c+1)] - x[max(c-1)]
        const float g0y[4] = { ce0.y - hl0, ce0.z - ce0.x, ce0.w - ce0.y, hr0 - ce0.z };
        const float g1y[4] = { ce1.y - hl1, ce1.z - ce1.x, ce1.w - ce1.y, hr1 - ce1.z };

#pragma unroll
        for (int q = 0; q < 4; q++) {
            const float n0  = fmaf(g0x[q], g0x[q], fmaf(g0y[q], g0y[q], EPS));
            const float n1  = fmaf(g1x[q], g1x[q], fmaf(g1y[q], g1y[q], EPS));
            const float dot = fmaf(g0x[q], g1x[q], g0y[q] * g1y[q]);
            // dot^2/(n0*n1) == (g0/|g0| . g1/|g1|)^2
            s += __fdividef(dot * dot, n0 * n1);
        }
    }

    // ---- reduction: 8 warps ----
#pragma unroll
    for (int off = 16; off > 0; off >>= 1)
        s += __shfl_xor_sync(0xFFFFFFFFu, s, off);

    const int wid = t >> 5;
    if (lane == 0) warp_part[wid] = s;
    __syncthreads();

    if (t == 0) {
        double bs = 0.0;
#pragma unroll
        for (int w = 0; w < 8; w++) bs += (double)warp_part[w];
        atomicAdd(&g_acc, bs);
        __threadfence();
        const unsigned prev = atomicAdd(&g_count, 1u);
        if (prev == NBLOCKS - 1) {
            const double total = atomicAdd(&g_acc, 0.0);
            out[0] = (float)(1.0 - total / (double)NPIX);
            g_acc = 0.0;          // reset for next graph replay
            g_count = 0u;
            __threadfence();
        }
    }
}

extern "C" void kernel_launch(void* const* d_in, const int* in_sizes, int n_in,
                              void* d_out, int out_size)
{
    const float* I0 = (const float*)d_in[0];
    const float* I1 = (const float*)d_in[1];
    float* out = (float*)d_out;

    ngf_kernel<<<NBLOCKS, 256>>>(I0, I1, out);
}

// round 7
// speedup vs baseline: 2.2164x; 1.0754x over previous
#include <cuda_runtime.h>
#include <cstdint>

#define IMG_W 512
#define IMG_H 512
#define PLANES 64
#define PLANE_STRIDE (IMG_H * IMG_W)
#define NPIX (PLANES * PLANE_STRIDE)
#define STRIP 16
#define STRIPS (IMG_H / STRIP)           // 32
#define NBLOCKS (PLANES * STRIPS)        // 2048
#define NSLOT 8                          // power-of-2 ring: % -> &
#define EPS 1e-10f

// persistent scratch (statically zero-init; last block resets each call)
__device__ double g_acc;
__device__ unsigned int g_count;

__device__ __forceinline__ void cp16(uint32_t dst, const float* src) {
    asm volatile("cp.async.cg.shared.global [%0], [%1], 16;" :: "r"(dst), "l"(src) : "memory");
}
__device__ __forceinline__ void cp_commit() {
    asm volatile("cp.async.commit_group;" ::: "memory");
}
__device__ __forceinline__ void cp_wait1() {
    asm volatile("cp.async.wait_group 1;" ::: "memory");
}
__device__ __forceinline__ void cp_wait0() {
    asm volatile("cp.async.wait_group 0;" ::: "memory");
}

__global__ void __launch_bounds__(256, 5) ngf_kernel(
    const float* __restrict__ I0, const float* __restrict__ I1,
    float* __restrict__ out)
{
    // ring slot s (k&7) holds one row pair: [img0: 512 f][img1: 512 f]
    __shared__ float ring[NSLOT * 1024];
    __shared__ float warp_part[8];

    const int t    = threadIdx.x;
    const int lane = t & 31;
    const int cg   = t & 127;            // float4 column group 0..127
    const int h    = t >> 7;             // 0/1: producer image AND compute row-half
    const int plane = blockIdx.x >> 5;
    const int strip = blockIdx.x & (STRIPS - 1);
    const int R0    = strip * STRIP;

    // producer: this thread copies rows of image h, 16B at column cg
    const float* __restrict__ lbase = (h ? I1 : I0) + plane * PLANE_STRIDE + (cg << 2);
    const uint32_t dstBase = (uint32_t)__cvta_generic_to_shared(ring) + (h << 11) + (cg << 4);

    // group j copies rows k = 2j, 2j+1 (global row clamp(R0-1+k)) of image h
    #define ISSUE_GROUP(j)                                                       \
        do {                                                                     \
            _Pragma("unroll")                                                    \
            for (int q = 0; q < 2; q++) {                                        \
                const int k = 2 * (j) + q;                                       \
                int g = R0 - 1 + k;                                              \
                g = max(0, min(g, IMG_H - 1));                                   \
                cp16(dstBase + ((k & 7) << 12), lbase + g * IMG_W);              \
            }                                                                    \
            cp_commit();                                                         \
        } while (0)

    // prologue: groups 0,1 (rows k=0..3)
    ISSUE_GROUP(0);
    ISSUE_GROUP(1);

    // hoisted edge-lane smem indices (clamped at image edge)
    const int il = max(4 * cg - 1, 0);
    const int ir = min(4 * cg + 4, IMG_W - 1);

    float4 up0, up1;      // carried: up@i = dn@(i-1)
    float s = 0.f;

#pragma unroll
    for (int i = 0; i < 8; i++) {
        if (i < 7) ISSUE_GROUP(i + 2);   // real groups 2..8
        else       cp_commit();          // keep group count uniform
        cp_wait1();                      // groups <= i+1 done -> rows k <= 2i+3
        __syncthreads();                 // all threads' copies visible; also
                                         // bounds laggards for ring-slot safety

        // ---- compute row r = R0 + 2i + h  (center k = 2i+1+h) ----
        const int kc = 2 * i + 1 + h;
        const float* cer = ring + ((kc & 7) << 10);
        const float* dnr = ring + (((kc + 1) & 7) << 10);

        if (i == 0) {   // first iter: load up row (k = h) directly
            const float* upr = ring + (h << 10);
            up0 = ((const float4*)upr)[cg];
            up1 = ((const float4*)(upr + 512))[cg];
        }
        const float4 ce0 = ((const float4*)cer)[cg];
        const float4 ce1 = ((const float4*)(cer + 512))[cg];
        const float4 dn0 = ((const float4*)dnr)[cg];
        const float4 dn1 = ((const float4*)(dnr + 512))[cg];

        // horizontal halo: shfl interior, warp-edge lanes patch from smem
        float hl0 = __shfl_up_sync(0xFFFFFFFFu, ce0.w, 1);
        float hr0 = __shfl_down_sync(0xFFFFFFFFu, ce0.x, 1);
        float hl1 = __shfl_up_sync(0xFFFFFFFFu, ce1.w, 1);
        float hr1 = __shfl_down_sync(0xFFFFFFFFu, ce1.x, 1);
        if (lane == 0)  { hl0 = cer[il];       hl1 = cer[512 + il]; }
        if (lane == 31) { hr0 = cer[ir];       hr1 = cer[512 + ir]; }

        // gx = x[min(r+1)] - x[max(r-1)]   (rows were loaded row-clamped)
        const float g0x[4] = { dn0.x - up0.x, dn0.y - up0.y, dn0.z - up0.z, dn0.w - up0.w };
        const float g1x[4] = { dn1.x - up1.x, dn1.y - up1.y, dn1.z - up1.z, dn1.w - up1.w };
        // gy = x[min(c+1)] - x[max(c-1)]
        const float g0y[4] = { ce0.y - hl0, ce0.z - ce0.x, ce0.w - ce0.y, hr0 - ce0.z };
        const float g1y[4] = { ce1.y - hl1, ce1.z - ce1.x, ce1.w - ce1.y, hr1 - ce1.z };

#pragma unroll
        for (int q = 0; q < 4; q++) {
            const float n0  = fmaf(g0x[q], g0x[q], fmaf(g0y[q], g0y[q], EPS));
            const float n1  = fmaf(g1x[q], g1x[q], fmaf(g1y[q], g1y[q], EPS));
            const float dot = fmaf(g0x[q], g1x[q], g0y[q] * g1y[q]);
            // dot^2/(n0*n1) == (g0/|g0| . g1/|g1|)^2
            s += __fdividef(dot * dot, n0 * n1);
        }

        // carry: up@(i+1) (k=2i+2+h) == dn@i
        up0 = dn0; up1 = dn1;
    }

    cp_wait0();    // retire all groups before smem reuse / exit

    // ---- reduction: 8 warps ----
#pragma unroll
    for (int off = 16; off > 0; off >>= 1)
        s += __shfl_xor_sync(0xFFFFFFFFu, s, off);

    const int wid = t >> 5;
    if (lane == 0) warp_part[wid] = s;
    __syncthreads();

    if (t == 0) {
        double bs = 0.0;
#pragma unroll
        for (int w = 0; w < 8; w++) bs += (double)warp_part[w];
        atomicAdd(&g_acc, bs);
        __threadfence();
        const unsigned prev = atomicAdd(&g_count, 1u);
        if (prev == NBLOCKS - 1) {
            const double total = atomicAdd(&g_acc, 0.0);
            out[0] = (float)(1.0 - total / (double)NPIX);
            g_acc = 0.0;          // reset for next graph replay
            g_count = 0u;
            __threadfence();
        }
    }
}

extern "C" void kernel_launch(void* const* d_in, const int* in_sizes, int n_in,
                              void* d_out, int out_size)
{
    const float* I0 = (const float*)d_in[0];
    const float* I1 = (const float*)d_in[1];
    float* out = (float*)d_out;

    ngf_kernel<<<NBLOCKS, 256>>>(I0, I1, out);
}